// round 7
// baseline (speedup 1.0000x reference)
#include <cuda_runtime.h>
#include <math.h>
#include <stdint.h>

#define NB  8
#define SEQ 2048
#define DIM 512
#define SCALE 0.04419417382415922f  // 1/sqrt(512)

// tf32-rounded (and k-permuted) copies of GEMM inputs + permuted weights.
// Permutation within each 32-col chunk: phys = (k%4)*8 + k/4, so that for
// m16n8k8 tf32 fragments, each thread's 8 needed words per row are contiguous.
__device__ float g_Qr[(size_t)NB * SEQ * DIM];
__device__ float g_Kr[(size_t)NB * SEQ * DIM];
__device__ float g_Vr[(size_t)NB * SEQ * DIM];
__device__ float g_Wp[(size_t)NB * SEQ * SEQ];   // permuted softmax weights

// ---------------------------------------------------------------------------
// helpers
// ---------------------------------------------------------------------------
__device__ __forceinline__ uint32_t f2tf(float x) {
    uint32_t u;
    asm("cvt.rna.tf32.f32 %0, %1;" : "=r"(u) : "f"(x));
    return u;
}
__device__ __forceinline__ float f2tf_f(float x) {
    return __uint_as_float(f2tf(x));
}

__device__ __forceinline__ uint32_t smem_u32(const void* p) {
    uint32_t a;
    asm("{ .reg .u64 t; cvta.to.shared.u64 t, %1; cvt.u32.u64 %0, t; }"
        : "=r"(a) : "l"(p));
    return a;
}

#define CP_ASYNC16(dst_u32, src_ptr) \
    asm volatile("cp.async.cg.shared.global [%0], [%1], 16;" \
                 :: "r"(dst_u32), "l"(src_ptr) : "memory")
#define CP_COMMIT() asm volatile("cp.async.commit_group;" ::: "memory")
#define CP_WAIT1()  asm volatile("cp.async.wait_group 1;" ::: "memory")

__device__ __forceinline__ void mma_tf32(float* d, const uint32_t* a, const uint32_t* b) {
    asm volatile(
        "mma.sync.aligned.m16n8k8.row.col.f32.tf32.tf32.f32 "
        "{%0,%1,%2,%3}, {%4,%5,%6,%7}, {%8,%9}, {%0,%1,%2,%3};\n"
        : "+f"(d[0]), "+f"(d[1]), "+f"(d[2]), "+f"(d[3])
        : "r"(a[0]), "r"(a[1]), "r"(a[2]), "r"(a[3]),
          "r"(b[0]), "r"(b[1]));
}

// ---------------------------------------------------------------------------
// Pre-pass: tf32 round + chunk-permute (for K-major MMA operands).
// Each thread produces 4 consecutive PHYS words (one float4 store), gathering
// logical positions k = (p%8)*4 + p/8 within the 32-word chunk.
// ---------------------------------------------------------------------------
__global__ __launch_bounds__(256)
void round_perm_kernel(const float* __restrict__ in, float* __restrict__ out) {
    size_t p4 = ((size_t)blockIdx.x * 256 + threadIdx.x) * 4;
    size_t rowbase = p4 & ~(size_t)31;   // start of the 32-word chunk
    int po = (int)(p4 & 31);             // phys offset within chunk (mult of 4)
    float4 v;
    float* vp = &v.x;
#pragma unroll
    for (int j = 0; j < 4; j++) {
        int p = po + j;
        int k = (p & 7) * 4 + (p >> 3);
        vp[j] = f2tf_f(in[rowbase + k]);
    }
    *reinterpret_cast<float4*>(&out[p4]) = v;
}

// plain tf32 rounding (V: consumed N-major, no permute)
__global__ __launch_bounds__(256)
void round_tf32_kernel(const float* __restrict__ in, float* __restrict__ out) {
    size_t i = (size_t)blockIdx.x * 256 + threadIdx.x;
    float4 v = reinterpret_cast<const float4*>(in)[i];
    v.x = f2tf_f(v.x); v.y = f2tf_f(v.y);
    v.z = f2tf_f(v.z); v.w = f2tf_f(v.w);
    reinterpret_cast<float4*>(out)[i] = v;
}

// ---------------------------------------------------------------------------
// GEMM1: logits[b,i,j] = SCALE * sum_d Qr[b,i,d] * Kr[b,j,d]
// 128x128 tile, BK=32, 3-stage cp.async, 256 threads (8 warps 2x4),
// warp tile 64x32. Operands pre-permuted -> all fragment loads are LDS.128.
// ---------------------------------------------------------------------------
#define QK_TW 4608  // words per tile per stage: 128*36

__global__ __launch_bounds__(256, 2)
void qk_mma_kernel(const float* __restrict__ Q, const float* __restrict__ Km,
                   float* __restrict__ attn) {
    extern __shared__ __align__(16) uint32_t sh[];
    uint32_t* As = sh;
    uint32_t* Bs = sh + 3 * QK_TW;
    const uint32_t as_b = smem_u32(As);
    const uint32_t bs_b = smem_u32(Bs);

    const int b  = blockIdx.z;
    const int i0 = blockIdx.y * 128;
    const int j0 = blockIdx.x * 128;

    const float* q = Q  + (size_t)b * SEQ * DIM + (size_t)i0 * DIM;
    const float* k = Km + (size_t)b * SEQ * DIM + (size_t)j0 * DIM;
    float* out = attn + (size_t)b * SEQ * SEQ;

    const int tid  = threadIdx.x;
    const int warp = tid >> 5;
    const int lane = tid & 31;
    const int r = lane >> 2;
    const int c = lane & 3;
    const int wm = (warp & 1) * 64;
    const int wn = (warp >> 1) * 32;

    int lrow[4], lc4[4];
#pragma unroll
    for (int t = 0; t < 4; t++) {
        int f = tid + t * 256;
        lrow[t] = f >> 3;
        lc4[t]  = f & 7;
    }

    float acc[16][4];
#pragma unroll
    for (int i = 0; i < 16; i++)
#pragma unroll
        for (int j = 0; j < 4; j++) acc[i][j] = 0.0f;

    const int NT = DIM / 32;  // 16 chunks

#pragma unroll
    for (int pc = 0; pc < 2; pc++) {
#pragma unroll
        for (int t = 0; t < 4; t++) {
            uint32_t so = (pc * QK_TW + lrow[t] * 36 + lc4[t] * 4) * 4;
            CP_ASYNC16(as_b + so, &q[(size_t)lrow[t] * DIM + pc * 32 + lc4[t] * 4]);
            CP_ASYNC16(bs_b + so, &k[(size_t)lrow[t] * DIM + pc * 32 + lc4[t] * 4]);
        }
        CP_COMMIT();
    }

    for (int kt = 0; kt < NT; kt++) {
        const int s = kt % 3;
        CP_WAIT1();
        __syncthreads();

        if (kt + 2 < NT) {
            const int s2 = (kt + 2) % 3;
            const int k0 = (kt + 2) * 32;
#pragma unroll
            for (int t = 0; t < 4; t++) {
                uint32_t so = (s2 * QK_TW + lrow[t] * 36 + lc4[t] * 4) * 4;
                CP_ASYNC16(as_b + so, &q[(size_t)lrow[t] * DIM + k0 + lc4[t] * 4]);
                CP_ASYNC16(bs_b + so, &k[(size_t)lrow[t] * DIM + k0 + lc4[t] * 4]);
            }
        }
        CP_COMMIT();

        const uint32_t* Ast = As + s * QK_TW;
        const uint32_t* Bst = Bs + s * QK_TW;

        // hoist all B fragments for this chunk: 8 LDS.128
        uint32_t bfr[4][8];
#pragma unroll
        for (int nt = 0; nt < 4; nt++) {
            int base = (wn + nt * 8 + r) * 36 + c * 8;
            *reinterpret_cast<uint4*>(&bfr[nt][0]) =
                *reinterpret_cast<const uint4*>(&Bst[base]);
            *reinterpret_cast<uint4*>(&bfr[nt][4]) =
                *reinterpret_cast<const uint4*>(&Bst[base + 4]);
        }

#pragma unroll
        for (int mt = 0; mt < 4; mt++) {
            int rb = wm + mt * 16;
            uint32_t alo[8], ahi[8];
            int blo = (rb + r) * 36 + c * 8;
            int bhi = (rb + r + 8) * 36 + c * 8;
            *reinterpret_cast<uint4*>(&alo[0]) =
                *reinterpret_cast<const uint4*>(&Ast[blo]);
            *reinterpret_cast<uint4*>(&alo[4]) =
                *reinterpret_cast<const uint4*>(&Ast[blo + 4]);
            *reinterpret_cast<uint4*>(&ahi[0]) =
                *reinterpret_cast<const uint4*>(&Ast[bhi]);
            *reinterpret_cast<uint4*>(&ahi[4]) =
                *reinterpret_cast<const uint4*>(&Ast[bhi + 4]);
#pragma unroll
            for (int ks = 0; ks < 4; ks++) {
                uint32_t af[4] = {alo[2 * ks], ahi[2 * ks],
                                  alo[2 * ks + 1], ahi[2 * ks + 1]};
#pragma unroll
                for (int nt = 0; nt < 4; nt++) {
                    uint32_t bf[2] = {bfr[nt][2 * ks], bfr[nt][2 * ks + 1]};
                    mma_tf32(acc[mt * 4 + nt], af, bf);
                }
            }
        }
    }

#pragma unroll
    for (int mt = 0; mt < 4; mt++) {
#pragma unroll
        for (int nt = 0; nt < 4; nt++) {
            float* a = acc[mt * 4 + nt];
            int row = i0 + wm + mt * 16 + r;
            int col = j0 + wn + nt * 8 + c * 2;
            float2 v0 = make_float2(a[0] * SCALE, a[1] * SCALE);
            float2 v1 = make_float2(a[2] * SCALE, a[3] * SCALE);
            *reinterpret_cast<float2*>(&out[(size_t)row * SEQ + col]) = v0;
            *reinterpret_cast<float2*>(&out[(size_t)(row + 8) * SEQ + col]) = v1;
        }
    }
}

// ---------------------------------------------------------------------------
// Softmax over each row of 2048. Writes logical (tf32-rounded) weights to
// d_out and chunk-permuted copy to g_Wp for GEMM2.
// ---------------------------------------------------------------------------
__global__ __launch_bounds__(256)
void softmax_kernel(float* __restrict__ attn, float* __restrict__ Wp) {
    const size_t row = blockIdx.x;
    float4* p4 = reinterpret_cast<float4*>(attn + row * SEQ);
    float* wp = Wp + row * SEQ;
    const int tid = threadIdx.x;

    float4 v0 = p4[tid];
    float4 v1 = p4[tid + 256];

    float m = fmaxf(fmaxf(fmaxf(v0.x, v0.y), fmaxf(v0.z, v0.w)),
                    fmaxf(fmaxf(v1.x, v1.y), fmaxf(v1.z, v1.w)));
#pragma unroll
    for (int o = 16; o > 0; o >>= 1)
        m = fmaxf(m, __shfl_xor_sync(0xffffffffu, m, o));

    __shared__ float sm[8];
    __shared__ float ss[8];
    if ((tid & 31) == 0) sm[tid >> 5] = m;
    __syncthreads();
    m = sm[0];
#pragma unroll
    for (int i = 1; i < 8; i++) m = fmaxf(m, sm[i]);

    float4 e0, e1;
    e0.x = __expf(v0.x - m); e0.y = __expf(v0.y - m);
    e0.z = __expf(v0.z - m); e0.w = __expf(v0.w - m);
    e1.x = __expf(v1.x - m); e1.y = __expf(v1.y - m);
    e1.z = __expf(v1.z - m); e1.w = __expf(v1.w - m);

    float s = (e0.x + e0.y + e0.z + e0.w) + (e1.x + e1.y + e1.z + e1.w);
#pragma unroll
    for (int o = 16; o > 0; o >>= 1)
        s += __shfl_xor_sync(0xffffffffu, s, o);
    if ((tid & 31) == 0) ss[tid >> 5] = s;
    __syncthreads();
    s = ss[0];
#pragma unroll
    for (int i = 1; i < 8; i++) s += ss[i];

    float inv = 1.0f / s;
    e0.x = f2tf_f(e0.x * inv); e0.y = f2tf_f(e0.y * inv);
    e0.z = f2tf_f(e0.z * inv); e0.w = f2tf_f(e0.w * inv);
    e1.x = f2tf_f(e1.x * inv); e1.y = f2tf_f(e1.y * inv);
    e1.z = f2tf_f(e1.z * inv); e1.w = f2tf_f(e1.w * inv);
    p4[tid] = e0;
    p4[tid + 256] = e1;

    // permuted store: logical k = tid*4 + j (+1024); phys = chunk*32 + j*8 + (tid%8)
    const int lane8 = tid & 7;
    const int cb0 = (tid >> 3) * 32;           // chunk base for e0
    const int cb1 = 1024 + cb0;                // chunk base for e1
    const float* ep0 = &e0.x;
    const float* ep1 = &e1.x;
#pragma unroll
    for (int j = 0; j < 4; j++) {
        wp[cb0 + j * 8 + lane8] = ep0[j];
        wp[cb1 + j * 8 + lane8] = ep1[j];
    }
}

// ---------------------------------------------------------------------------
// GEMM2: ctx[b,i,d] = sum_j Wp[b,i,j] * Vr[b,j,d]
// 128x128 tile, BK=32, 3-stage. A (Wp) permuted -> LDS.128 fragment loads;
// B (Vr) N-major [k][n] pad 132 -> scalar fragment loads (small).
// ---------------------------------------------------------------------------
#define AV_AW 4608   // 128*36
#define AV_BW 4224   // 32*132

__global__ __launch_bounds__(256, 2)
void av_mma_kernel(const float* __restrict__ W, const float* __restrict__ V,
                   float* __restrict__ ctx) {
    extern __shared__ __align__(16) uint32_t sh[];
    uint32_t* As = sh;
    uint32_t* Bs = sh + 3 * AV_AW;
    const uint32_t as_b = smem_u32(As);
    const uint32_t bs_b = smem_u32(Bs);

    const int b  = blockIdx.z;
    const int i0 = blockIdx.y * 128;
    const int n0 = blockIdx.x * 128;

    const float* w = W + (size_t)b * SEQ * SEQ + (size_t)i0 * SEQ;
    const float* v = V + (size_t)b * SEQ * DIM;
    float* o = ctx + (size_t)b * SEQ * DIM;

    const int tid  = threadIdx.x;
    const int warp = tid >> 5;
    const int lane = tid & 31;
    const int r = lane >> 2;
    const int c = lane & 3;
    const int wm = (warp & 1) * 64;
    const int wn = (warp >> 1) * 32;

    int arow[4], ac4[4], brow[4], bc4[4];
#pragma unroll
    for (int t = 0; t < 4; t++) {
        int f = tid + t * 256;
        arow[t] = f >> 3;  ac4[t] = f & 7;
        brow[t] = f >> 5;  bc4[t] = f & 31;
    }

    float acc[16][4];
#pragma unroll
    for (int i = 0; i < 16; i++)
#pragma unroll
        for (int j = 0; j < 4; j++) acc[i][j] = 0.0f;

    const int NT = SEQ / 32;  // 64 chunks

#pragma unroll
    for (int pc = 0; pc < 2; pc++) {
#pragma unroll
        for (int t = 0; t < 4; t++) {
            uint32_t sa = (pc * AV_AW + arow[t] * 36 + ac4[t] * 4) * 4;
            CP_ASYNC16(as_b + sa, &w[(size_t)arow[t] * SEQ + pc * 32 + ac4[t] * 4]);
            uint32_t sb = (pc * AV_BW + brow[t] * 132 + bc4[t] * 4) * 4;
            CP_ASYNC16(bs_b + sb, &v[(size_t)(pc * 32 + brow[t]) * DIM + n0 + bc4[t] * 4]);
        }
        CP_COMMIT();
    }

    for (int kt = 0; kt < NT; kt++) {
        const int s = kt % 3;
        CP_WAIT1();
        __syncthreads();

        if (kt + 2 < NT) {
            const int s2 = (kt + 2) % 3;
            const int k0 = (kt + 2) * 32;
#pragma unroll
            for (int t = 0; t < 4; t++) {
                uint32_t sa = (s2 * AV_AW + arow[t] * 36 + ac4[t] * 4) * 4;
                CP_ASYNC16(as_b + sa, &w[(size_t)arow[t] * SEQ + k0 + ac4[t] * 4]);
                uint32_t sb = (s2 * AV_BW + brow[t] * 132 + bc4[t] * 4) * 4;
                CP_ASYNC16(bs_b + sb, &v[(size_t)(k0 + brow[t]) * DIM + n0 + bc4[t] * 4]);
            }
        }
        CP_COMMIT();

        const uint32_t* Ast = As + s * AV_AW;
        const uint32_t* Bst = Bs + s * AV_BW;

        // hoist B fragments: 32 scalar LDS
        uint32_t bfr[4][4][2];
#pragma unroll
        for (int ks = 0; ks < 4; ks++)
#pragma unroll
            for (int nt = 0; nt < 4; nt++) {
                int nb = wn + nt * 8;
                bfr[ks][nt][0] = Bst[(ks * 8 + c) * 132 + nb + r];
                bfr[ks][nt][1] = Bst[(ks * 8 + c + 4) * 132 + nb + r];
            }

#pragma unroll
        for (int mt = 0; mt < 4; mt++) {
            int rb = wm + mt * 16;
            uint32_t alo[8], ahi[8];
            int blo = (rb + r) * 36 + c * 8;
            int bhi = (rb + r + 8) * 36 + c * 8;
            *reinterpret_cast<uint4*>(&alo[0]) =
                *reinterpret_cast<const uint4*>(&Ast[blo]);
            *reinterpret_cast<uint4*>(&alo[4]) =
                *reinterpret_cast<const uint4*>(&Ast[blo + 4]);
            *reinterpret_cast<uint4*>(&ahi[0]) =
                *reinterpret_cast<const uint4*>(&Ast[bhi]);
            *reinterpret_cast<uint4*>(&ahi[4]) =
                *reinterpret_cast<const uint4*>(&Ast[bhi + 4]);
#pragma unroll
            for (int ks = 0; ks < 4; ks++) {
                uint32_t af[4] = {alo[2 * ks], ahi[2 * ks],
                                  alo[2 * ks + 1], ahi[2 * ks + 1]};
#pragma unroll
                for (int nt = 0; nt < 4; nt++)
                    mma_tf32(acc[mt * 4 + nt], af, bfr[ks][nt]);
            }
        }
    }

#pragma unroll
    for (int mt = 0; mt < 4; mt++) {
#pragma unroll
        for (int nt = 0; nt < 4; nt++) {
            float* a = acc[mt * 4 + nt];
            int row = i0 + wm + mt * 16 + r;
            int col = n0 + wn + nt * 8 + c * 2;
            float2 v0 = make_float2(a[0], a[1]);
            float2 v1 = make_float2(a[2], a[3]);
            *reinterpret_cast<float2*>(&o[(size_t)row * DIM + col]) = v0;
            *reinterpret_cast<float2*>(&o[(size_t)(row + 8) * DIM + col]) = v1;
        }
    }
}

// ---------------------------------------------------------------------------
extern "C" void kernel_launch(void* const* d_in, const int* in_sizes, int n_in,
                              void* d_out, int out_size) {
    const float* Q = (const float*)d_in[0];
    const float* K = (const float*)d_in[1];
    const float* V = (const float*)d_in[2];

    float* ctx  = (float*)d_out;                      // [8, 2048, 512]
    float* attn = ctx + (size_t)NB * SEQ * DIM;       // [8, 2048, 2048]

    float *Qr, *Kr, *Vr, *Wp;
    cudaGetSymbolAddress((void**)&Qr, g_Qr);
    cudaGetSymbolAddress((void**)&Kr, g_Kr);
    cudaGetSymbolAddress((void**)&Vr, g_Vr);
    cudaGetSymbolAddress((void**)&Wp, g_Wp);

    constexpr int QK_SMEM = 3 * QK_TW * 2 * 4;             // 110592 B
    constexpr int AV_SMEM = 3 * (AV_AW + AV_BW) * 4;       // 105984 B
    cudaFuncSetAttribute(qk_mma_kernel,
                         cudaFuncAttributeMaxDynamicSharedMemorySize, QK_SMEM);
    cudaFuncSetAttribute(av_mma_kernel,
                         cudaFuncAttributeMaxDynamicSharedMemorySize, AV_SMEM);

    const int n4 = NB * SEQ * DIM / 4;
    round_perm_kernel<<<n4 / 256, 256>>>(Q, Qr);
    round_perm_kernel<<<n4 / 256, 256>>>(K, Kr);
    round_tf32_kernel<<<n4 / 256, 256>>>(V, Vr);

    dim3 g1(SEQ / 128, SEQ / 128, NB);
    qk_mma_kernel<<<g1, 256, QK_SMEM>>>(Qr, Kr, attn);

    softmax_kernel<<<NB * SEQ, 256>>>(attn, Wp);

    dim3 g2(DIM / 128, SEQ / 128, NB);
    av_mma_kernel<<<g2, 256, AV_SMEM>>>(Wp, Vr, ctx);
}

// round 9
// speedup vs baseline: 1.0920x; 1.0920x over previous
#include <cuda_runtime.h>
#include <math.h>
#include <stdint.h>

#define NB  8
#define SEQ 2048
#define DIM 512
#define SCALE 0.04419417382415922f  // 1/sqrt(512)

// tf32-rounded copies of the GEMM inputs (pre-pass). Q is pre-scaled by SCALE.
__device__ float g_Qr[(size_t)NB * SEQ * DIM];
__device__ float g_Kr[(size_t)NB * SEQ * DIM];
__device__ float g_Vr[(size_t)NB * SEQ * DIM];

// ---------------------------------------------------------------------------
// helpers
// ---------------------------------------------------------------------------
__device__ __forceinline__ uint32_t f2tf(float x) {
    uint32_t u;
    asm("cvt.rna.tf32.f32 %0, %1;" : "=r"(u) : "f"(x));
    return u;
}
__device__ __forceinline__ float f2tf_f(float x) {
    return __uint_as_float(f2tf(x));
}

__device__ __forceinline__ uint32_t smem_u32(const void* p) {
    uint32_t a;
    asm("{ .reg .u64 t; cvta.to.shared.u64 t, %1; cvt.u32.u64 %0, t; }"
        : "=r"(a) : "l"(p));
    return a;
}

#define CP_ASYNC16(dst_u32, src_ptr) \
    asm volatile("cp.async.cg.shared.global [%0], [%1], 16;" \
                 :: "r"(dst_u32), "l"(src_ptr) : "memory")
#define CP_COMMIT() asm volatile("cp.async.commit_group;" ::: "memory")
#define CP_WAIT1()  asm volatile("cp.async.wait_group 1;" ::: "memory")

__device__ __forceinline__ void mma_tf32(float* d, const uint32_t* a, const uint32_t* b) {
    asm volatile(
        "mma.sync.aligned.m16n8k8.row.col.f32.tf32.tf32.f32 "
        "{%0,%1,%2,%3}, {%4,%5,%6,%7}, {%8,%9}, {%0,%1,%2,%3};\n"
        : "+f"(d[0]), "+f"(d[1]), "+f"(d[2]), "+f"(d[3])
        : "r"(a[0]), "r"(a[1]), "r"(a[2]), "r"(a[3]),
          "r"(b[0]), "r"(b[1]));
}

// ---------------------------------------------------------------------------
// Fused tf32 rounding pre-pass for Q (pre-scaled), K, V.
// blockIdx.y selects the tensor.
// ---------------------------------------------------------------------------
__global__ __launch_bounds__(256)
void round_tf32_fused_kernel(const float* __restrict__ Q,
                             const float* __restrict__ K,
                             const float* __restrict__ V,
                             float* __restrict__ Qr,
                             float* __restrict__ Kr,
                             float* __restrict__ Vr) {
    const int which = blockIdx.y;
    const float* in  = (which == 0) ? Q  : (which == 1) ? K  : V;
    float*       out = (which == 0) ? Qr : (which == 1) ? Kr : Vr;
    const float s = (which == 0) ? SCALE : 1.0f;

    size_t i = (size_t)blockIdx.x * 256 + threadIdx.x;
    float4 v = reinterpret_cast<const float4*>(in)[i];
    v.x = f2tf_f(v.x * s); v.y = f2tf_f(v.y * s);
    v.z = f2tf_f(v.z * s); v.w = f2tf_f(v.w * s);
    reinterpret_cast<float4*>(out)[i] = v;
}

// ---------------------------------------------------------------------------
// GEMM1: logits[b,i,j] = sum_d Qr[b,i,d] * Kr[b,j,d]   (Qr pre-scaled)
// 128x128 tile, BK=32, 3-stage cp.async pipeline, 256 threads (8 warps),
// warp tile 64x32, 4x4 m16n8k8 tf32 tiles. (Exact R4 structure.)
// ---------------------------------------------------------------------------
#define QK_TW 4608  // words per tile per stage: 128*36

__global__ __launch_bounds__(256)
void qk_mma_kernel(const float* __restrict__ Q, const float* __restrict__ Km,
                   float* __restrict__ attn) {
    extern __shared__ __align__(16) uint32_t sh[];
    uint32_t* As = sh;                // 3 stages
    uint32_t* Bs = sh + 3 * QK_TW;    // 3 stages
    const uint32_t as_b = smem_u32(As);
    const uint32_t bs_b = smem_u32(Bs);

    const int b  = blockIdx.z;
    const int i0 = blockIdx.y * 128;
    const int j0 = blockIdx.x * 128;

    const float* q = Q  + (size_t)b * SEQ * DIM + (size_t)i0 * DIM;
    const float* k = Km + (size_t)b * SEQ * DIM + (size_t)j0 * DIM;
    float* out = attn + (size_t)b * SEQ * SEQ;

    const int tid  = threadIdx.x;
    const int warp = tid >> 5;
    const int lane = tid & 31;
    const int r = lane >> 2;
    const int c = lane & 3;
    const int wm = (warp & 1) * 64;
    const int wn = (warp >> 1) * 32;

    int lrow[4], lc4[4];
#pragma unroll
    for (int t = 0; t < 4; t++) {
        int f = tid + t * 256;
        lrow[t] = f >> 3;
        lc4[t]  = f & 7;
    }

    float acc[16][4];
#pragma unroll
    for (int i = 0; i < 16; i++)
#pragma unroll
        for (int j = 0; j < 4; j++) acc[i][j] = 0.0f;

    const int NT = DIM / 32;  // 16 chunks

#pragma unroll
    for (int pc = 0; pc < 2; pc++) {
#pragma unroll
        for (int t = 0; t < 4; t++) {
            uint32_t so = (pc * QK_TW + lrow[t] * 36 + lc4[t] * 4) * 4;
            CP_ASYNC16(as_b + so, &q[(size_t)lrow[t] * DIM + pc * 32 + lc4[t] * 4]);
            CP_ASYNC16(bs_b + so, &k[(size_t)lrow[t] * DIM + pc * 32 + lc4[t] * 4]);
        }
        CP_COMMIT();
    }

    for (int kt = 0; kt < NT; kt++) {
        const int s = kt % 3;
        CP_WAIT1();
        __syncthreads();

        if (kt + 2 < NT) {
            const int s2 = (kt + 2) % 3;
            const int k0 = (kt + 2) * 32;
#pragma unroll
            for (int t = 0; t < 4; t++) {
                uint32_t so = (s2 * QK_TW + lrow[t] * 36 + lc4[t] * 4) * 4;
                CP_ASYNC16(as_b + so, &q[(size_t)lrow[t] * DIM + k0 + lc4[t] * 4]);
                CP_ASYNC16(bs_b + so, &k[(size_t)lrow[t] * DIM + k0 + lc4[t] * 4]);
            }
        }
        CP_COMMIT();

        const uint32_t* Ast = As + s * QK_TW;
        const uint32_t* Bst = Bs + s * QK_TW;
#pragma unroll
        for (int ks = 0; ks < 4; ks++) {
            uint32_t au[4][4], bu[4][2];
#pragma unroll
            for (int mt = 0; mt < 4; mt++) {
                int rb = wm + mt * 16;
                au[mt][0] = Ast[(rb + r) * 36 + ks * 8 + c];
                au[mt][1] = Ast[(rb + r + 8) * 36 + ks * 8 + c];
                au[mt][2] = Ast[(rb + r) * 36 + ks * 8 + c + 4];
                au[mt][3] = Ast[(rb + r + 8) * 36 + ks * 8 + c + 4];
            }
#pragma unroll
            for (int nt = 0; nt < 4; nt++) {
                int nb = wn + nt * 8;
                bu[nt][0] = Bst[(nb + r) * 36 + ks * 8 + c];
                bu[nt][1] = Bst[(nb + r) * 36 + ks * 8 + c + 4];
            }
#pragma unroll
            for (int mt = 0; mt < 4; mt++)
#pragma unroll
                for (int nt = 0; nt < 4; nt++)
                    mma_tf32(acc[mt * 4 + nt], au[mt], bu[nt]);
        }
    }

#pragma unroll
    for (int mt = 0; mt < 4; mt++) {
#pragma unroll
        for (int nt = 0; nt < 4; nt++) {
            float* a = acc[mt * 4 + nt];
            int row = i0 + wm + mt * 16 + r;
            int col = j0 + wn + nt * 8 + c * 2;
            float2 v0 = make_float2(a[0], a[1]);
            float2 v1 = make_float2(a[2], a[3]);
            *reinterpret_cast<float2*>(&out[(size_t)row * SEQ + col]) = v0;
            *reinterpret_cast<float2*>(&out[(size_t)(row + 8) * SEQ + col]) = v1;
        }
    }
}

// ---------------------------------------------------------------------------
// Softmax: one WARP per row of 2048 (16 float4 per lane, register-resident,
// no block barriers). Output rounded to tf32 for GEMM2.
// ---------------------------------------------------------------------------
__global__ __launch_bounds__(256)
void softmax_kernel(float* __restrict__ attn) {
    const int warp = threadIdx.x >> 5;
    const int lane = threadIdx.x & 31;
    const size_t row = (size_t)blockIdx.x * 8 + warp;
    float4* p4 = reinterpret_cast<float4*>(attn + row * SEQ);

    float4 v[16];
#pragma unroll
    for (int i = 0; i < 16; i++) v[i] = p4[lane + 32 * i];

    float m = -3.4e38f;
#pragma unroll
    for (int i = 0; i < 16; i++) {
        m = fmaxf(m, fmaxf(fmaxf(v[i].x, v[i].y), fmaxf(v[i].z, v[i].w)));
    }
#pragma unroll
    for (int o = 16; o > 0; o >>= 1)
        m = fmaxf(m, __shfl_xor_sync(0xffffffffu, m, o));

    float s = 0.0f;
#pragma unroll
    for (int i = 0; i < 16; i++) {
        v[i].x = __expf(v[i].x - m);
        v[i].y = __expf(v[i].y - m);
        v[i].z = __expf(v[i].z - m);
        v[i].w = __expf(v[i].w - m);
        s += (v[i].x + v[i].y) + (v[i].z + v[i].w);
    }
#pragma unroll
    for (int o = 16; o > 0; o >>= 1)
        s += __shfl_xor_sync(0xffffffffu, s, o);

    const float inv = 1.0f / s;
#pragma unroll
    for (int i = 0; i < 16; i++) {
        v[i].x = f2tf_f(v[i].x * inv);
        v[i].y = f2tf_f(v[i].y * inv);
        v[i].z = f2tf_f(v[i].z * inv);
        v[i].w = f2tf_f(v[i].w * inv);
        p4[lane + 32 * i] = v[i];
    }
}

// ---------------------------------------------------------------------------
// GEMM2: ctx[b,i,d] = sum_j W[b,i,j] * Vr[b,j,d]
// 128x128 tile, BK=32, 3-stage cp.async pipeline. (Exact R4 structure.)
// A: [m][k] pad 36;  B: [k][n] pad 132 (N-major).
// ---------------------------------------------------------------------------
#define AV_AW 4608   // 128*36
#define AV_BW 4224   // 32*132

__global__ __launch_bounds__(256)
void av_mma_kernel(const float* __restrict__ W, const float* __restrict__ V,
                   float* __restrict__ ctx) {
    extern __shared__ __align__(16) uint32_t sh[];
    uint32_t* As = sh;                 // 3 stages of AV_AW
    uint32_t* Bs = sh + 3 * AV_AW;     // 3 stages of AV_BW
    const uint32_t as_b = smem_u32(As);
    const uint32_t bs_b = smem_u32(Bs);

    const int b  = blockIdx.z;
    const int i0 = blockIdx.y * 128;
    const int n0 = blockIdx.x * 128;

    const float* w = W + (size_t)b * SEQ * SEQ + (size_t)i0 * SEQ;
    const float* v = V + (size_t)b * SEQ * DIM;
    float* o = ctx + (size_t)b * SEQ * DIM;

    const int tid  = threadIdx.x;
    const int warp = tid >> 5;
    const int lane = tid & 31;
    const int r = lane >> 2;
    const int c = lane & 3;
    const int wm = (warp & 1) * 64;
    const int wn = (warp >> 1) * 32;

    int arow[4], ac4[4], brow[4], bc4[4];
#pragma unroll
    for (int t = 0; t < 4; t++) {
        int f = tid + t * 256;
        arow[t] = f >> 3;  ac4[t] = f & 7;
        brow[t] = f >> 5;  bc4[t] = f & 31;
    }

    float acc[16][4];
#pragma unroll
    for (int i = 0; i < 16; i++)
#pragma unroll
        for (int j = 0; j < 4; j++) acc[i][j] = 0.0f;

    const int NT = SEQ / 32;  // 64 chunks

#pragma unroll
    for (int pc = 0; pc < 2; pc++) {
#pragma unroll
        for (int t = 0; t < 4; t++) {
            uint32_t sa = (pc * AV_AW + arow[t] * 36 + ac4[t] * 4) * 4;
            CP_ASYNC16(as_b + sa, &w[(size_t)arow[t] * SEQ + pc * 32 + ac4[t] * 4]);
            uint32_t sb = (pc * AV_BW + brow[t] * 132 + bc4[t] * 4) * 4;
            CP_ASYNC16(bs_b + sb, &v[(size_t)(pc * 32 + brow[t]) * DIM + n0 + bc4[t] * 4]);
        }
        CP_COMMIT();
    }

    for (int kt = 0; kt < NT; kt++) {
        const int s = kt % 3;
        CP_WAIT1();
        __syncthreads();

        if (kt + 2 < NT) {
            const int s2 = (kt + 2) % 3;
            const int k0 = (kt + 2) * 32;
#pragma unroll
            for (int t = 0; t < 4; t++) {
                uint32_t sa = (s2 * AV_AW + arow[t] * 36 + ac4[t] * 4) * 4;
                CP_ASYNC16(as_b + sa, &w[(size_t)arow[t] * SEQ + k0 + ac4[t] * 4]);
                uint32_t sb = (s2 * AV_BW + brow[t] * 132 + bc4[t] * 4) * 4;
                CP_ASYNC16(bs_b + sb, &v[(size_t)(k0 + brow[t]) * DIM + n0 + bc4[t] * 4]);
            }
        }
        CP_COMMIT();

        const uint32_t* Ast = As + s * AV_AW;
        const uint32_t* Bst = Bs + s * AV_BW;
#pragma unroll
        for (int ks = 0; ks < 4; ks++) {
            uint32_t au[4][4], bu[4][2];
#pragma unroll
            for (int mt = 0; mt < 4; mt++) {
                int rb = wm + mt * 16;
                au[mt][0] = Ast[(rb + r) * 36 + ks * 8 + c];
                au[mt][1] = Ast[(rb + r + 8) * 36 + ks * 8 + c];
                au[mt][2] = Ast[(rb + r) * 36 + ks * 8 + c + 4];
                au[mt][3] = Ast[(rb + r + 8) * 36 + ks * 8 + c + 4];
            }
#pragma unroll
            for (int nt = 0; nt < 4; nt++) {
                int nb = wn + nt * 8;
                bu[nt][0] = Bst[(ks * 8 + c) * 132 + nb + r];
                bu[nt][1] = Bst[(ks * 8 + c + 4) * 132 + nb + r];
            }
#pragma unroll
            for (int mt = 0; mt < 4; mt++)
#pragma unroll
                for (int nt = 0; nt < 4; nt++)
                    mma_tf32(acc[mt * 4 + nt], au[mt], bu[nt]);
        }
    }

#pragma unroll
    for (int mt = 0; mt < 4; mt++) {
#pragma unroll
        for (int nt = 0; nt < 4; nt++) {
            float* a = acc[mt * 4 + nt];
            int row = i0 + wm + mt * 16 + r;
            int col = n0 + wn + nt * 8 + c * 2;
            float2 v0 = make_float2(a[0], a[1]);
            float2 v1 = make_float2(a[2], a[3]);
            *reinterpret_cast<float2*>(&o[(size_t)row * DIM + col]) = v0;
            *reinterpret_cast<float2*>(&o[(size_t)(row + 8) * DIM + col]) = v1;
        }
    }
}

// ---------------------------------------------------------------------------
extern "C" void kernel_launch(void* const* d_in, const int* in_sizes, int n_in,
                              void* d_out, int out_size) {
    const float* Q = (const float*)d_in[0];
    const float* K = (const float*)d_in[1];
    const float* V = (const float*)d_in[2];

    float* ctx  = (float*)d_out;                      // [8, 2048, 512]
    float* attn = ctx + (size_t)NB * SEQ * DIM;       // [8, 2048, 2048]

    float *Qr, *Kr, *Vr;
    cudaGetSymbolAddress((void**)&Qr, g_Qr);
    cudaGetSymbolAddress((void**)&Kr, g_Kr);
    cudaGetSymbolAddress((void**)&Vr, g_Vr);

    constexpr int QK_SMEM = 3 * QK_TW * 2 * 4;             // 110592 B
    constexpr int AV_SMEM = 3 * (AV_AW + AV_BW) * 4;       // 105984 B
    cudaFuncSetAttribute(qk_mma_kernel,
                         cudaFuncAttributeMaxDynamicSharedMemorySize, QK_SMEM);
    cudaFuncSetAttribute(av_mma_kernel,
                         cudaFuncAttributeMaxDynamicSharedMemorySize, AV_SMEM);

    const int n4 = NB * SEQ * DIM / 4;  // 2M float4 per tensor
    round_tf32_fused_kernel<<<dim3(n4 / 256, 3), 256>>>(Q, K, V, Qr, Kr, Vr);

    dim3 g1(SEQ / 128, SEQ / 128, NB);
    qk_mma_kernel<<<g1, 256, QK_SMEM>>>(Qr, Kr, attn);

    softmax_kernel<<<NB * SEQ / 8, 256>>>(attn);

    dim3 g2(DIM / 128, SEQ / 128, NB);
    av_mma_kernel<<<g2, 256, AV_SMEM>>>(attn, Vr, ctx);
}

// round 10
// speedup vs baseline: 1.1966x; 1.0958x over previous
#include <cuda_runtime.h>
#include <math.h>
#include <stdint.h>

#define NB  8
#define SEQ 2048
#define DIM 512
#define SCALE 0.04419417382415922f  // 1/sqrt(512)

// tf32-rounded copies: Qr pre-scaled, Kr, and V transposed to [b][d][j].
__device__ float g_Qr[(size_t)NB * SEQ * DIM];
__device__ float g_Kr[(size_t)NB * SEQ * DIM];
__device__ float g_Vt[(size_t)NB * DIM * SEQ];

// ---------------------------------------------------------------------------
// helpers
// ---------------------------------------------------------------------------
__device__ __forceinline__ uint32_t f2tf(float x) {
    uint32_t u;
    asm("cvt.rna.tf32.f32 %0, %1;" : "=r"(u) : "f"(x));
    return u;
}
__device__ __forceinline__ float f2tf_f(float x) {
    return __uint_as_float(f2tf(x));
}

__device__ __forceinline__ uint32_t smem_u32(const void* p) {
    uint32_t a;
    asm("{ .reg .u64 t; cvta.to.shared.u64 t, %1; cvt.u32.u64 %0, t; }"
        : "=r"(a) : "l"(p));
    return a;
}

#define CP_ASYNC16(dst_u32, src_ptr) \
    asm volatile("cp.async.cg.shared.global [%0], [%1], 16;" \
                 :: "r"(dst_u32), "l"(src_ptr) : "memory")
#define CP_COMMIT() asm volatile("cp.async.commit_group;" ::: "memory")
#define CP_WAIT1()  asm volatile("cp.async.wait_group 1;" ::: "memory")

__device__ __forceinline__ void mma_tf32(float* d, const uint32_t* a, const uint32_t* b) {
    asm volatile(
        "mma.sync.aligned.m16n8k8.row.col.f32.tf32.tf32.f32 "
        "{%0,%1,%2,%3}, {%4,%5,%6,%7}, {%8,%9}, {%0,%1,%2,%3};\n"
        : "+f"(d[0]), "+f"(d[1]), "+f"(d[2]), "+f"(d[3])
        : "r"(a[0]), "r"(a[1]), "r"(a[2]), "r"(a[3]),
          "r"(b[0]), "r"(b[1]));
}

__device__ __forceinline__ void ldsm_x4(uint32_t* d, uint32_t addr) {
    asm volatile(
        "ldmatrix.sync.aligned.m8n8.x4.shared.b16 {%0,%1,%2,%3}, [%4];"
        : "=r"(d[0]), "=r"(d[1]), "=r"(d[2]), "=r"(d[3]) : "r"(addr));
}
__device__ __forceinline__ void ldsm_x2(uint32_t* d, uint32_t addr) {
    asm volatile(
        "ldmatrix.sync.aligned.m8n8.x2.shared.b16 {%0,%1}, [%2];"
        : "=r"(d[0]), "=r"(d[1]) : "r"(addr));
}

// ---------------------------------------------------------------------------
// Pre-pass 1: tf32 round Q (pre-scaled by SCALE) and K.
// ---------------------------------------------------------------------------
__global__ __launch_bounds__(256)
void round_qk_kernel(const float* __restrict__ Q, const float* __restrict__ K,
                     float* __restrict__ Qr, float* __restrict__ Kr) {
    const int which = blockIdx.y;
    const float* in  = which ? K : Q;
    float*       out = which ? Kr : Qr;
    const float s = which ? 1.0f : SCALE;

    size_t i = (size_t)blockIdx.x * 256 + threadIdx.x;
    float4 v = reinterpret_cast<const float4*>(in)[i];
    v.x = f2tf_f(v.x * s); v.y = f2tf_f(v.y * s);
    v.z = f2tf_f(v.z * s); v.w = f2tf_f(v.w * s);
    reinterpret_cast<float4*>(out)[i] = v;
}

// ---------------------------------------------------------------------------
// Pre-pass 2: transpose V to [b][d][j] with tf32 rounding.
// ---------------------------------------------------------------------------
__global__ __launch_bounds__(256)
void transpose_v_kernel(const float* __restrict__ V, float* __restrict__ Vt) {
    __shared__ float t[32][33];
    const int b = blockIdx.z;
    const int j0 = blockIdx.x * 32;
    const int d0 = blockIdx.y * 32;
    const int tx = threadIdx.x, ty = threadIdx.y;  // 32 x 8
    const float* v = V + (size_t)b * SEQ * DIM;
    float* o = Vt + (size_t)b * DIM * SEQ;
#pragma unroll
    for (int i = 0; i < 4; i++)
        t[ty + i * 8][tx] = f2tf_f(v[(size_t)(j0 + ty + i * 8) * DIM + d0 + tx]);
    __syncthreads();
#pragma unroll
    for (int i = 0; i < 4; i++)
        o[(size_t)(d0 + ty + i * 8) * SEQ + j0 + tx] = t[tx][ty + i * 8];
}

// ---------------------------------------------------------------------------
// Unified NT GEMM: C[m,n] = sum_k A[m,k] * B[n,k]
// 128x128 tile, BK=32, 3-stage cp.async, 256 threads (8 warps 2x4),
// warp tile 64x32, fragments via ldmatrix (LDSM).
// A rows m (M=SEQ), B rows n (per-tile 128 of NB_ROWS), both K-major, pad 36.
// ---------------------------------------------------------------------------
#define G_TW 4608  // words per tile per stage: 128*36

template <int KTOT, int LDA, int LDB, int LDC>
__global__ __launch_bounds__(256)
void gemm_nt_kernel(const float* __restrict__ Ag, const float* __restrict__ Bg,
                    float* __restrict__ Cg) {
    extern __shared__ __align__(16) uint32_t sh[];
    uint32_t* As = sh;                // 3 stages
    uint32_t* Bs = sh + 3 * G_TW;     // 3 stages
    const uint32_t as_b = smem_u32(As);
    const uint32_t bs_b = smem_u32(Bs);

    const int z  = blockIdx.z;
    const int i0 = blockIdx.y * 128;
    const int n0 = blockIdx.x * 128;

    const float* a = Ag + (size_t)z * SEQ * LDA + (size_t)i0 * LDA;
    const float* bp = Bg + (size_t)z * (size_t)SEQ * DIM + (size_t)n0 * LDB;
    float* out = Cg + (size_t)z * SEQ * LDC;

    const int tid  = threadIdx.x;
    const int warp = tid >> 5;
    const int lane = tid & 31;
    const int wm = (warp & 1) * 64;
    const int wn = (warp >> 1) * 32;

    // ldmatrix base addresses (bytes, within a stage)
    const int lr = lane & 7;
    const int g  = lane >> 3;                   // 0..3
    const uint32_t a_off = ((wm + (g & 1) * 8 + lr) * 36 + (g >> 1) * 4) * 4;
    const int l2 = lane & 15;
    const uint32_t b_off = ((wn + (l2 & 7)) * 36 + (l2 >> 3) * 4) * 4;

    // epilogue coords
    const int r = lane >> 2;
    const int c = lane & 3;

    int lrow[4], lc4[4];
#pragma unroll
    for (int t = 0; t < 4; t++) {
        int f = tid + t * 256;
        lrow[t] = f >> 3;
        lc4[t]  = f & 7;
    }

    float acc[16][4];
#pragma unroll
    for (int i = 0; i < 16; i++)
#pragma unroll
        for (int j = 0; j < 4; j++) acc[i][j] = 0.0f;

    const int NT = KTOT / 32;

#pragma unroll
    for (int pc = 0; pc < 2; pc++) {
#pragma unroll
        for (int t = 0; t < 4; t++) {
            uint32_t so = (pc * G_TW + lrow[t] * 36 + lc4[t] * 4) * 4;
            CP_ASYNC16(as_b + so, &a[(size_t)lrow[t] * LDA + pc * 32 + lc4[t] * 4]);
            CP_ASYNC16(bs_b + so, &bp[(size_t)lrow[t] * LDB + pc * 32 + lc4[t] * 4]);
        }
        CP_COMMIT();
    }

    for (int kt = 0; kt < NT; kt++) {
        const int s = kt % 3;
        CP_WAIT1();
        __syncthreads();

        if (kt + 2 < NT) {
            const int s2 = (kt + 2) % 3;
            const int k0 = (kt + 2) * 32;
#pragma unroll
            for (int t = 0; t < 4; t++) {
                uint32_t so = (s2 * G_TW + lrow[t] * 36 + lc4[t] * 4) * 4;
                CP_ASYNC16(as_b + so, &a[(size_t)lrow[t] * LDA + k0 + lc4[t] * 4]);
                CP_ASYNC16(bs_b + so, &bp[(size_t)lrow[t] * LDB + k0 + lc4[t] * 4]);
            }
        }
        CP_COMMIT();

        const uint32_t a_s = as_b + s * (G_TW * 4) + a_off;
        const uint32_t b_s = bs_b + s * (G_TW * 4) + b_off;

#pragma unroll
        for (int ks = 0; ks < 4; ks++) {
            uint32_t au[4][4], bu[4][2];
#pragma unroll
            for (int mt = 0; mt < 4; mt++)
                ldsm_x4(au[mt], a_s + mt * 2304 + ks * 32);
#pragma unroll
            for (int nt = 0; nt < 4; nt++)
                ldsm_x2(bu[nt], b_s + nt * 1152 + ks * 32);
#pragma unroll
            for (int mt = 0; mt < 4; mt++)
#pragma unroll
                for (int nt = 0; nt < 4; nt++)
                    mma_tf32(acc[mt * 4 + nt], au[mt], bu[nt]);
        }
    }

#pragma unroll
    for (int mt = 0; mt < 4; mt++) {
#pragma unroll
        for (int nt = 0; nt < 4; nt++) {
            float* av = acc[mt * 4 + nt];
            int row = i0 + wm + mt * 16 + r;
            int col = n0 + wn + nt * 8 + c * 2;
            float2 v0 = make_float2(av[0], av[1]);
            float2 v1 = make_float2(av[2], av[3]);
            *reinterpret_cast<float2*>(&out[(size_t)row * LDC + col]) = v0;
            *reinterpret_cast<float2*>(&out[(size_t)(row + 8) * LDC + col]) = v1;
        }
    }
}

// ---------------------------------------------------------------------------
// Softmax: one WARP per row of 2048 (register-resident, shfl reductions).
// Output rounded to tf32 for GEMM2.
// ---------------------------------------------------------------------------
__global__ __launch_bounds__(256)
void softmax_kernel(float* __restrict__ attn) {
    const int warp = threadIdx.x >> 5;
    const int lane = threadIdx.x & 31;
    const size_t row = (size_t)blockIdx.x * 8 + warp;
    float4* p4 = reinterpret_cast<float4*>(attn + row * SEQ);

    float4 v[16];
#pragma unroll
    for (int i = 0; i < 16; i++) v[i] = p4[lane + 32 * i];

    float m = -3.4e38f;
#pragma unroll
    for (int i = 0; i < 16; i++) {
        m = fmaxf(m, fmaxf(fmaxf(v[i].x, v[i].y), fmaxf(v[i].z, v[i].w)));
    }
#pragma unroll
    for (int o = 16; o > 0; o >>= 1)
        m = fmaxf(m, __shfl_xor_sync(0xffffffffu, m, o));

    float s = 0.0f;
#pragma unroll
    for (int i = 0; i < 16; i++) {
        v[i].x = __expf(v[i].x - m);
        v[i].y = __expf(v[i].y - m);
        v[i].z = __expf(v[i].z - m);
        v[i].w = __expf(v[i].w - m);
        s += (v[i].x + v[i].y) + (v[i].z + v[i].w);
    }
#pragma unroll
    for (int o = 16; o > 0; o >>= 1)
        s += __shfl_xor_sync(0xffffffffu, s, o);

    const float inv = 1.0f / s;
#pragma unroll
    for (int i = 0; i < 16; i++) {
        v[i].x = f2tf_f(v[i].x * inv);
        v[i].y = f2tf_f(v[i].y * inv);
        v[i].z = f2tf_f(v[i].z * inv);
        v[i].w = f2tf_f(v[i].w * inv);
        p4[lane + 32 * i] = v[i];
    }
}

// ---------------------------------------------------------------------------
extern "C" void kernel_launch(void* const* d_in, const int* in_sizes, int n_in,
                              void* d_out, int out_size) {
    const float* Q = (const float*)d_in[0];
    const float* K = (const float*)d_in[1];
    const float* V = (const float*)d_in[2];

    float* ctx  = (float*)d_out;                      // [8, 2048, 512]
    float* attn = ctx + (size_t)NB * SEQ * DIM;       // [8, 2048, 2048]

    float *Qr, *Kr, *Vt;
    cudaGetSymbolAddress((void**)&Qr, g_Qr);
    cudaGetSymbolAddress((void**)&Kr, g_Kr);
    cudaGetSymbolAddress((void**)&Vt, g_Vt);

    constexpr int G_SMEM = 3 * G_TW * 2 * 4;  // 110592 B
    cudaFuncSetAttribute(gemm_nt_kernel<DIM, DIM, DIM, SEQ>,
                         cudaFuncAttributeMaxDynamicSharedMemorySize, G_SMEM);
    cudaFuncSetAttribute(gemm_nt_kernel<SEQ, SEQ, SEQ, DIM>,
                         cudaFuncAttributeMaxDynamicSharedMemorySize, G_SMEM);

    const int n4 = NB * SEQ * DIM / 4;
    round_qk_kernel<<<dim3(n4 / 256, 2), 256>>>(Q, K, Qr, Kr);
    transpose_v_kernel<<<dim3(SEQ / 32, DIM / 32, NB), dim3(32, 8)>>>(V, Vt);

    // GEMM1: attn = (SCALE*Q) K^T
    dim3 g1(SEQ / 128, SEQ / 128, NB);
    gemm_nt_kernel<DIM, DIM, DIM, SEQ><<<g1, 256, G_SMEM>>>(Qr, Kr, attn);

    softmax_kernel<<<NB * SEQ / 8, 256>>>(attn);

    // GEMM2: ctx = W Vt^T  (A rows=i over SEQ, B rows=d over DIM, k=j)
    dim3 g2(DIM / 128, SEQ / 128, NB);
    gemm_nt_kernel<SEQ, SEQ, SEQ, DIM><<<g2, 256, G_SMEM>>>(attn, Vt, ctx);
}

// round 11
// speedup vs baseline: 1.3414x; 1.1210x over previous
#include <cuda_runtime.h>
#include <math.h>
#include <stdint.h>

#define NB  8
#define SEQ 2048
#define DIM 512
#define SCALE 0.04419417382415922f  // 1/sqrt(512)

// tf32-rounded copies: Qr pre-scaled, Kr, and V transposed to [b][d][j].
__device__ float g_Qr[(size_t)NB * SEQ * DIM];
__device__ float g_Kr[(size_t)NB * SEQ * DIM];
__device__ float g_Vt[(size_t)NB * DIM * SEQ];

// ---------------------------------------------------------------------------
// helpers
// ---------------------------------------------------------------------------
__device__ __forceinline__ uint32_t f2tf(float x) {
    uint32_t u;
    asm("cvt.rna.tf32.f32 %0, %1;" : "=r"(u) : "f"(x));
    return u;
}
__device__ __forceinline__ float f2tf_f(float x) {
    return __uint_as_float(f2tf(x));
}

__device__ __forceinline__ uint32_t smem_u32(const void* p) {
    uint32_t a;
    asm("{ .reg .u64 t; cvta.to.shared.u64 t, %1; cvt.u32.u64 %0, t; }"
        : "=r"(a) : "l"(p));
    return a;
}

#define CP_ASYNC16(dst_u32, src_ptr) \
    asm volatile("cp.async.cg.shared.global [%0], [%1], 16;" \
                 :: "r"(dst_u32), "l"(src_ptr) : "memory")
#define CP_COMMIT() asm volatile("cp.async.commit_group;" ::: "memory")
#define CP_WAIT1()  asm volatile("cp.async.wait_group 1;" ::: "memory")

__device__ __forceinline__ void mma_tf32(float* d, const uint32_t* a, const uint32_t* b) {
    asm volatile(
        "mma.sync.aligned.m16n8k8.row.col.f32.tf32.tf32.f32 "
        "{%0,%1,%2,%3}, {%4,%5,%6,%7}, {%8,%9}, {%0,%1,%2,%3};\n"
        : "+f"(d[0]), "+f"(d[1]), "+f"(d[2]), "+f"(d[3])
        : "r"(a[0]), "r"(a[1]), "r"(a[2]), "r"(a[3]),
          "r"(b[0]), "r"(b[1]));
}

__device__ __forceinline__ void ldsm_x4(uint32_t* d, uint32_t addr) {
    asm volatile(
        "ldmatrix.sync.aligned.m8n8.x4.shared.b16 {%0,%1,%2,%3}, [%4];"
        : "=r"(d[0]), "=r"(d[1]), "=r"(d[2]), "=r"(d[3]) : "r"(addr));
}

// ---------------------------------------------------------------------------
// Pre-pass 1: tf32 round Q (pre-scaled by SCALE) and K.
// ---------------------------------------------------------------------------
__global__ __launch_bounds__(256)
void round_qk_kernel(const float* __restrict__ Q, const float* __restrict__ K,
                     float* __restrict__ Qr, float* __restrict__ Kr) {
    const int which = blockIdx.y;
    const float* in  = which ? K : Q;
    float*       out = which ? Kr : Qr;
    const float s = which ? 1.0f : SCALE;

    size_t i = (size_t)blockIdx.x * 256 + threadIdx.x;
    float4 v = reinterpret_cast<const float4*>(in)[i];
    v.x = f2tf_f(v.x * s); v.y = f2tf_f(v.y * s);
    v.z = f2tf_f(v.z * s); v.w = f2tf_f(v.w * s);
    reinterpret_cast<float4*>(out)[i] = v;
}

// ---------------------------------------------------------------------------
// Pre-pass 2: transpose V to [b][d][j] with tf32 rounding.
// ---------------------------------------------------------------------------
__global__ __launch_bounds__(256)
void transpose_v_kernel(const float* __restrict__ V, float* __restrict__ Vt) {
    __shared__ float t[32][33];
    const int b = blockIdx.z;
    const int j0 = blockIdx.x * 32;
    const int d0 = blockIdx.y * 32;
    const int tx = threadIdx.x, ty = threadIdx.y;  // 32 x 8
    const float* v = V + (size_t)b * SEQ * DIM;
    float* o = Vt + (size_t)b * DIM * SEQ;
#pragma unroll
    for (int i = 0; i < 4; i++)
        t[ty + i * 8][tx] = f2tf_f(v[(size_t)(j0 + ty + i * 8) * DIM + d0 + tx]);
    __syncthreads();
#pragma unroll
    for (int i = 0; i < 4; i++)
        o[(size_t)(d0 + ty + i * 8) * SEQ + j0 + tx] = t[tx][ty + i * 8];
}

// ---------------------------------------------------------------------------
// Unified NT GEMM: C[m,n] = sum_k A[m,k] * B[n,k]
// 128x128 tile, BK=32, 3-stage cp.async, 256 threads (8 warps 2x4),
// warp tile 64x32, fragments via ldmatrix.
// B fragments: two n-tiles per ldmatrix.x4 (paired).
// Next-chunk cp.async issued AFTER ks=0 compute to unblock the tensor pipe.
// ---------------------------------------------------------------------------
#define G_TW 4608  // words per tile per stage: 128*36

template <int KTOT, int LDA, int LDB, int LDC>
__global__ __launch_bounds__(256, 2)
void gemm_nt_kernel(const float* __restrict__ Ag, const float* __restrict__ Bg,
                    float* __restrict__ Cg) {
    extern __shared__ __align__(16) uint32_t sh[];
    uint32_t* As = sh;                // 3 stages
    uint32_t* Bs = sh + 3 * G_TW;     // 3 stages
    const uint32_t as_b = smem_u32(As);
    const uint32_t bs_b = smem_u32(Bs);

    const int z  = blockIdx.z;
    const int i0 = blockIdx.y * 128;
    const int n0 = blockIdx.x * 128;

    const float* a = Ag + (size_t)z * SEQ * LDA + (size_t)i0 * LDA;
    const float* bp = Bg + (size_t)z * (size_t)SEQ * DIM + (size_t)n0 * LDB;
    float* out = Cg + (size_t)z * SEQ * LDC;

    const int tid  = threadIdx.x;
    const int warp = tid >> 5;
    const int lane = tid & 31;
    const int wm = (warp & 1) * 64;
    const int wn = (warp >> 1) * 32;

    // ldmatrix per-lane addresses (bytes, within a stage)
    const int lr = lane & 7;
    const int g  = lane >> 3;                   // 0..3
    // A x4: matrices = (row groups +0,+8) x (k halves 0,4)
    const uint32_t a_off = ((wm + (g & 1) * 8 + lr) * 36 + (g >> 1) * 4) * 4;
    // B paired x4: groups 0/1 = n-tile (pair base), k half 0/1;
    //              groups 2/3 = n-tile +1,        k half 0/1
    const uint32_t b_off = ((wn + (g >> 1) * 8 + lr) * 36 + (g & 1) * 4) * 4;

    // epilogue coords
    const int r = lane >> 2;
    const int c = lane & 3;

    int lrow[4], lc4[4];
#pragma unroll
    for (int t = 0; t < 4; t++) {
        int f = tid + t * 256;
        lrow[t] = f >> 3;
        lc4[t]  = f & 7;
    }

    float acc[16][4];
#pragma unroll
    for (int i = 0; i < 16; i++)
#pragma unroll
        for (int j = 0; j < 4; j++) acc[i][j] = 0.0f;

    const int NT = KTOT / 32;

#pragma unroll
    for (int pc = 0; pc < 2; pc++) {
#pragma unroll
        for (int t = 0; t < 4; t++) {
            uint32_t so = (pc * G_TW + lrow[t] * 36 + lc4[t] * 4) * 4;
            CP_ASYNC16(as_b + so, &a[(size_t)lrow[t] * LDA + pc * 32 + lc4[t] * 4]);
            CP_ASYNC16(bs_b + so, &bp[(size_t)lrow[t] * LDB + pc * 32 + lc4[t] * 4]);
        }
        CP_COMMIT();
    }

    for (int kt = 0; kt < NT; kt++) {
        const int s = kt % 3;
        CP_WAIT1();
        __syncthreads();

        const uint32_t a_s = as_b + s * (G_TW * 4) + a_off;
        const uint32_t b_s = bs_b + s * (G_TW * 4) + b_off;

        // ---- ks = 0: start the tensor pipe before issuing next loads ----
        {
            uint32_t au[4][4], bu[2][4];
#pragma unroll
            for (int mt = 0; mt < 4; mt++)
                ldsm_x4(au[mt], a_s + mt * 2304);
#pragma unroll
            for (int np = 0; np < 2; np++)
                ldsm_x4(bu[np], b_s + np * 2304);
#pragma unroll
            for (int mt = 0; mt < 4; mt++)
#pragma unroll
                for (int nt = 0; nt < 4; nt++)
                    mma_tf32(acc[mt * 4 + nt], au[mt], &bu[nt >> 1][(nt & 1) * 2]);
        }

        // ---- issue next chunk's loads (hidden behind remaining compute) ----
        if (kt + 2 < NT) {
            const int s2 = (kt + 2) % 3;
            const int k0 = (kt + 2) * 32;
#pragma unroll
            for (int t = 0; t < 4; t++) {
                uint32_t so = (s2 * G_TW + lrow[t] * 36 + lc4[t] * 4) * 4;
                CP_ASYNC16(as_b + so, &a[(size_t)lrow[t] * LDA + k0 + lc4[t] * 4]);
                CP_ASYNC16(bs_b + so, &bp[(size_t)lrow[t] * LDB + k0 + lc4[t] * 4]);
            }
        }
        CP_COMMIT();

        // ---- ks = 1..3 ----
#pragma unroll
        for (int ks = 1; ks < 4; ks++) {
            uint32_t au[4][4], bu[2][4];
#pragma unroll
            for (int mt = 0; mt < 4; mt++)
                ldsm_x4(au[mt], a_s + mt * 2304 + ks * 32);
#pragma unroll
            for (int np = 0; np < 2; np++)
                ldsm_x4(bu[np], b_s + np * 2304 + ks * 32);
#pragma unroll
            for (int mt = 0; mt < 4; mt++)
#pragma unroll
                for (int nt = 0; nt < 4; nt++)
                    mma_tf32(acc[mt * 4 + nt], au[mt], &bu[nt >> 1][(nt & 1) * 2]);
        }
    }

#pragma unroll
    for (int mt = 0; mt < 4; mt++) {
#pragma unroll
        for (int nt = 0; nt < 4; nt++) {
            float* av = acc[mt * 4 + nt];
            int row = i0 + wm + mt * 16 + r;
            int col = n0 + wn + nt * 8 + c * 2;
            float2 v0 = make_float2(av[0], av[1]);
            float2 v1 = make_float2(av[2], av[3]);
            *reinterpret_cast<float2*>(&out[(size_t)row * LDC + col]) = v0;
            *reinterpret_cast<float2*>(&out[(size_t)(row + 8) * LDC + col]) = v1;
        }
    }
}

// ---------------------------------------------------------------------------
// Softmax: one WARP per row of 2048 (register-resident, shfl reductions).
// Output rounded to tf32 for GEMM2.
// ---------------------------------------------------------------------------
__global__ __launch_bounds__(256)
void softmax_kernel(float* __restrict__ attn) {
    const int warp = threadIdx.x >> 5;
    const int lane = threadIdx.x & 31;
    const size_t row = (size_t)blockIdx.x * 8 + warp;
    float4* p4 = reinterpret_cast<float4*>(attn + row * SEQ);

    float4 v[16];
#pragma unroll
    for (int i = 0; i < 16; i++) v[i] = p4[lane + 32 * i];

    float m = -3.4e38f;
#pragma unroll
    for (int i = 0; i < 16; i++) {
        m = fmaxf(m, fmaxf(fmaxf(v[i].x, v[i].y), fmaxf(v[i].z, v[i].w)));
    }
#pragma unroll
    for (int o = 16; o > 0; o >>= 1)
        m = fmaxf(m, __shfl_xor_sync(0xffffffffu, m, o));

    float s = 0.0f;
#pragma unroll
    for (int i = 0; i < 16; i++) {
        v[i].x = __expf(v[i].x - m);
        v[i].y = __expf(v[i].y - m);
        v[i].z = __expf(v[i].z - m);
        v[i].w = __expf(v[i].w - m);
        s += (v[i].x + v[i].y) + (v[i].z + v[i].w);
    }
#pragma unroll
    for (int o = 16; o > 0; o >>= 1)
        s += __shfl_xor_sync(0xffffffffu, s, o);

    const float inv = 1.0f / s;
#pragma unroll
    for (int i = 0; i < 16; i++) {
        v[i].x = f2tf_f(v[i].x * inv);
        v[i].y = f2tf_f(v[i].y * inv);
        v[i].z = f2tf_f(v[i].z * inv);
        v[i].w = f2tf_f(v[i].w * inv);
        p4[lane + 32 * i] = v[i];
    }
}

// ---------------------------------------------------------------------------
extern "C" void kernel_launch(void* const* d_in, const int* in_sizes, int n_in,
                              void* d_out, int out_size) {
    const float* Q = (const float*)d_in[0];
    const float* K = (const float*)d_in[1];
    const float* V = (const float*)d_in[2];

    float* ctx  = (float*)d_out;                      // [8, 2048, 512]
    float* attn = ctx + (size_t)NB * SEQ * DIM;       // [8, 2048, 2048]

    float *Qr, *Kr, *Vt;
    cudaGetSymbolAddress((void**)&Qr, g_Qr);
    cudaGetSymbolAddress((void**)&Kr, g_Kr);
    cudaGetSymbolAddress((void**)&Vt, g_Vt);

    constexpr int G_SMEM = 3 * G_TW * 2 * 4;  // 110592 B
    cudaFuncSetAttribute(gemm_nt_kernel<DIM, DIM, DIM, SEQ>,
                         cudaFuncAttributeMaxDynamicSharedMemorySize, G_SMEM);
    cudaFuncSetAttribute(gemm_nt_kernel<SEQ, SEQ, SEQ, DIM>,
                         cudaFuncAttributeMaxDynamicSharedMemorySize, G_SMEM);

    const int n4 = NB * SEQ * DIM / 4;
    round_qk_kernel<<<dim3(n4 / 256, 2), 256>>>(Q, K, Qr, Kr);
    transpose_v_kernel<<<dim3(SEQ / 32, DIM / 32, NB), dim3(32, 8)>>>(V, Vt);

    // GEMM1: attn = (SCALE*Q) K^T
    dim3 g1(SEQ / 128, SEQ / 128, NB);
    gemm_nt_kernel<DIM, DIM, DIM, SEQ><<<g1, 256, G_SMEM>>>(Qr, Kr, attn);

    softmax_kernel<<<NB * SEQ / 8, 256>>>(attn);

    // GEMM2: ctx = W Vt^T  (A rows=i over SEQ, B rows=d over DIM, k=j)
    dim3 g2(DIM / 128, SEQ / 128, NB);
    gemm_nt_kernel<SEQ, SEQ, SEQ, DIM><<<g2, 256, G_SMEM>>>(attn, Vt, ctx);
}